// round 16
// baseline (speedup 1.0000x reference)
#include <cuda_runtime.h>
#include <cuda_fp16.h>
#include <math.h>
#include <stdint.h>

// ---------------- problem constants ----------------
#define BATCH   2
#define SEQ     512
#define DM      768
#define DI      1536
#define DS      16
#define M_TOT   (BATCH*SEQ)   // 1024
#define XZ_LD   (2*DI)        // 3072
#define XDBL_LD (DI + 2*DS)   // 1568
#define NX_PAD  1664

// ---------------- scratch ----------------
__device__ __half g_xh    [M_TOT * DM];
__device__ __half g_Winh  [XZ_LD * DM];
__device__ __half g_Wxh   [NX_PAD * DI];
__device__ __half g_Wdth  [DI * DI];
__device__ __half g_Wouth [DM * DI];
__device__ __half g_xconvh[M_TOT * DI];
__device__ __half g_xdblh [M_TOT * DI];
__device__ __half g_ypreh [DI * M_TOT];     // [d][bt] (k-major for G6 A)
__device__ float  g_xin   [M_TOT * DI];
__device__ float  g_zT    [DI * M_TOT];
__device__ float  g_xconvT[DI * M_TOT];
__device__ float  g_BT    [DS * M_TOT];
__device__ float  g_CT2   [DS * M_TOT];
__device__ float  g_deltaT[DI * M_TOT];

// ---------------- helpers (fast transcendental intrinsics) ----------------
__device__ __forceinline__ float softplusf(float x) {
    if (x > 20.f) return x;
    return __logf(1.f + __expf(x));
}
__device__ __forceinline__ float siluf(float x) {
    return x / (1.f + __expf(-x));
}
__device__ __forceinline__ void cpa16(uint32_t dst, const void* src) {
    asm volatile("cp.async.cg.shared.global [%0], [%1], 16;\n" :: "r"(dst), "l"(src));
}
__device__ __forceinline__ void cpa_commit() {
    asm volatile("cp.async.commit_group;\n" ::: "memory");
}
__device__ __forceinline__ void ldmx4(uint32_t* r, uint32_t addr) {
    asm volatile(
        "ldmatrix.sync.aligned.m8n8.x4.shared.b16 {%0,%1,%2,%3}, [%4];"
        : "=r"(r[0]), "=r"(r[1]), "=r"(r[2]), "=r"(r[3]) : "r"(addr));
}
__device__ __forceinline__ void ldmx4t(uint32_t* r, uint32_t addr) {
    asm volatile(
        "ldmatrix.sync.aligned.m8n8.x4.trans.shared.b16 {%0,%1,%2,%3}, [%4];"
        : "=r"(r[0]), "=r"(r[1]), "=r"(r[2]), "=r"(r[3]) : "r"(addr));
}
__device__ __forceinline__ void mma_f16(float* c, const uint32_t* a, const uint32_t* b) {
    asm volatile(
        "mma.sync.aligned.m16n8k16.row.col.f32.f16.f16.f32 "
        "{%0,%1,%2,%3}, {%4,%5,%6,%7}, {%8,%9}, {%0,%1,%2,%3};"
        : "+f"(c[0]), "+f"(c[1]), "+f"(c[2]), "+f"(c[3])
        : "r"(a[0]), "r"(a[1]), "r"(a[2]), "r"(a[3]), "r"(b[0]), "r"(b[1]));
}

// ---------------- fp16 GEMM: act(A @ W^T) ----------------
// A row-major [1024,K] half, W row-major [N,K] half. 64x128x32 tile,
// 256 threads = 8 warps of 32x32, 2 CTAs/SM, ldmatrix fragments,
// 5-stage cp.async, 3 in flight, one __syncthreads per k-iter.
#define GSTH 5
#define AROWH 40                               // 32 halves + 8 pad
#define HSTG_B ((64 + 128) * AROWH * 2)        // 15360 B per stage
#define HSMEM  (GSTH * HSTG_B)                 // 76800 B

template<int EPI>
__global__ __launch_bounds__(256, 2)
void hgemm(const __half* __restrict__ A, int lda,
           const __half* __restrict__ W, int ldw,
           const float* __restrict__ bias,
           float* __restrict__ C, int ldc, int K)
{
    extern __shared__ __align__(16) char smem[];
    const int tid = threadIdx.x, warp = tid >> 5, lane = tid & 31;
    const int bm = blockIdx.y * 64, bn = blockIdx.x * 128;
    const int wm = (warp & 1) * 32, wn = (warp >> 1) * 32;
    const uint32_t sbase = (uint32_t)__cvta_generic_to_shared(smem);

    const int lrow8 = (lane & 7) + ((lane >> 3) & 1) * 8;
    const int lk8   = (lane >> 4) * 8;

    float acc[2][4][4];
#pragma unroll
    for (int i = 0; i < 2; i++)
#pragma unroll
        for (int j = 0; j < 4; j++)
#pragma unroll
            for (int k = 0; k < 4; k++) acc[i][j][k] = 0.f;

    const int nIter = K / 32;

    auto load_stage = [&](int s, int kt) {
        const uint32_t aB = sbase + (uint32_t)s * HSTG_B;
        const uint32_t bB = aB + 64 * AROWH * 2;
        {
            const int row = tid >> 2, ch = tid & 3;
            cpa16(aB + (uint32_t)(row * AROWH + ch * 8) * 2,
                  A + (size_t)(bm + row) * lda + kt * 32 + ch * 8);
        }
#pragma unroll
        for (int p = 0; p < 2; p++) {
            const int idx = tid + p * 256;
            const int row = idx >> 2, ch = idx & 3;
            cpa16(bB + (uint32_t)(row * AROWH + ch * 8) * 2,
                  W + (size_t)(bn + row) * ldw + kt * 32 + ch * 8);
        }
    };

    load_stage(0, 0); cpa_commit();
    load_stage(1, 1); cpa_commit();
    load_stage(2, 2); cpa_commit();

    for (int it = 0; it < nIter; it++) {
        asm volatile("cp.async.wait_group 2;\n" ::: "memory");
        __syncthreads();

        const uint32_t stg = sbase + (uint32_t)(it % GSTH) * HSTG_B;
        const uint32_t stgB = stg + 64 * AROWH * 2;

        uint32_t af[2][2][4], bq[2][2][4];
#pragma unroll
        for (int ks = 0; ks < 2; ks++) {
#pragma unroll
            for (int mt = 0; mt < 2; mt++)
                ldmx4(af[ks][mt],
                      stg + (uint32_t)((wm + mt * 16 + lrow8) * AROWH + ks * 16 + lk8) * 2);
#pragma unroll
            for (int nh = 0; nh < 2; nh++)
                ldmx4(bq[ks][nh],
                      stgB + (uint32_t)((wn + nh * 16 + lrow8) * AROWH + ks * 16 + lk8) * 2);
        }

        if (it + 3 < nIter) load_stage((it + 3) % GSTH, it + 3);
        cpa_commit();

#pragma unroll
        for (int ks = 0; ks < 2; ks++) {
#pragma unroll
            for (int nt = 0; nt < 4; nt++) {
                uint32_t bf[2] = { bq[ks][nt >> 1][nt & 1], bq[ks][nt >> 1][(nt & 1) + 2] };
#pragma unroll
                for (int mt = 0; mt < 2; mt++)
                    mma_f16(acc[mt][nt], af[ks][mt], bf);
            }
        }
    }

    // ---- epilogue ----
#pragma unroll
    for (int mt = 0; mt < 2; mt++) {
        const int row = bm + wm + mt * 16 + (lane >> 2);
#pragma unroll
        for (int nt = 0; nt < 4; nt++) {
            const int col = bn + wn + nt * 8 + (lane & 3) * 2;
            const float v0 = acc[mt][nt][0], v1 = acc[mt][nt][1];
            const float v2 = acc[mt][nt][2], v3 = acc[mt][nt][3];
            if (EPI == 1) {
                const float b0 = bias[col], b1 = bias[col + 1];
                C[(size_t)col * ldc + row]            = softplusf(v0 + b0);
                C[(size_t)(col + 1) * ldc + row]      = softplusf(v1 + b1);
                C[(size_t)col * ldc + row + 8]        = softplusf(v2 + b0);
                C[(size_t)(col + 1) * ldc + row + 8]  = softplusf(v3 + b1);
            } else if (EPI == 2) {
                if (col < DI) {
                    *(float2*)(g_xin + (size_t)row * DI + col)       = make_float2(v0, v1);
                    *(float2*)(g_xin + (size_t)(row + 8) * DI + col) = make_float2(v2, v3);
                } else {
                    const int dd = col - DI;
                    g_zT[(size_t)dd * M_TOT + row]           = siluf(v0);
                    g_zT[(size_t)(dd + 1) * M_TOT + row]     = siluf(v1);
                    g_zT[(size_t)dd * M_TOT + row + 8]       = siluf(v2);
                    g_zT[(size_t)(dd + 1) * M_TOT + row + 8] = siluf(v3);
                }
            } else {  // EPI == 3
                if (col < DI) {
                    *(__half2*)(g_xdblh + (size_t)row * DI + col)       = __floats2half2_rn(v0, v1);
                    *(__half2*)(g_xdblh + (size_t)(row + 8) * DI + col) = __floats2half2_rn(v2, v3);
                } else if (col < DI + DS) {
                    const int nn = col - DI;
                    g_BT[(size_t)nn * M_TOT + row]           = v0;
                    g_BT[(size_t)(nn + 1) * M_TOT + row]     = v1;
                    g_BT[(size_t)nn * M_TOT + row + 8]       = v2;
                    g_BT[(size_t)(nn + 1) * M_TOT + row + 8] = v3;
                } else if (col < DI + 2 * DS) {
                    const int nn = col - DI - DS;
                    g_CT2[(size_t)nn * M_TOT + row]           = v0;
                    g_CT2[(size_t)(nn + 1) * M_TOT + row]     = v1;
                    g_CT2[(size_t)nn * M_TOT + row + 8]       = v2;
                    g_CT2[(size_t)(nn + 1) * M_TOT + row + 8] = v3;
                }
            }
        }
    }
}

// ---------------- G6: out = ypre @ W_out^T, A stored k-major [DI][1024] ----
#define AROWM 72                                   // 64 m-halves + 8 pad
#define G6STG ((32 * AROWM + 64 * AROWH) * 2)      // 9728 B
#define G6SMEM (GSTH * G6STG)                      // 48640 B

__global__ __launch_bounds__(256, 2)
void hgemm_g6(const __half* __restrict__ AT,   // [K][1024]
              const __half* __restrict__ W,    // [DM][K]
              float* __restrict__ C, int ldc, int K)
{
    extern __shared__ __align__(16) char smem[];
    const int tid = threadIdx.x, warp = tid >> 5, lane = tid & 31;
    const int bm = blockIdx.y * 64, bn = blockIdx.x * 64;
    const int wm = (warp & 1) * 32, wn = (warp >> 1) * 16;
    const uint32_t sbase = (uint32_t)__cvta_generic_to_shared(smem);

    const int lrow8 = (lane & 7) + ((lane >> 3) & 1) * 8;
    const int lk8   = (lane >> 4) * 8;
    const int trow = (lane & 7) + ((lane >> 4) & 1) * 8;
    const int tcol = ((lane >> 3) & 1) * 8;

    float acc[2][2][4];
#pragma unroll
    for (int i = 0; i < 2; i++)
#pragma unroll
        for (int j = 0; j < 2; j++)
#pragma unroll
            for (int k = 0; k < 4; k++) acc[i][j][k] = 0.f;

    const int nIter = K / 32;

    auto load_stage = [&](int s, int kt) {
        const uint32_t aB = sbase + (uint32_t)s * G6STG;
        const uint32_t bB = aB + 32 * AROWM * 2;
        {
            const int row = tid >> 3, ch = tid & 7;
            cpa16(aB + (uint32_t)(row * AROWM + ch * 8) * 2,
                  AT + (size_t)(kt * 32 + row) * M_TOT + bm + ch * 8);
        }
        {
            const int row = tid >> 2, ch = tid & 3;
            cpa16(bB + (uint32_t)(row * AROWH + ch * 8) * 2,
                  W + (size_t)(bn + row) * K + kt * 32 + ch * 8);
        }
    };

    load_stage(0, 0); cpa_commit();
    load_stage(1, 1); cpa_commit();
    load_stage(2, 2); cpa_commit();

    for (int it = 0; it < nIter; it++) {
        asm volatile("cp.async.wait_group 2;\n" ::: "memory");
        __syncthreads();

        const uint32_t stg = sbase + (uint32_t)(it % GSTH) * G6STG;
        const uint32_t stgB = stg + 32 * AROWM * 2;

#pragma unroll
        for (int ks = 0; ks < 2; ks++) {
            uint32_t af[2][4], bq[4];
#pragma unroll
            for (int mt = 0; mt < 2; mt++)
                ldmx4t(af[mt],
                       stg + (uint32_t)((ks * 16 + trow) * AROWM + wm + mt * 16 + tcol) * 2);
            ldmx4(bq, stgB + (uint32_t)((wn + lrow8) * AROWH + ks * 16 + lk8) * 2);
#pragma unroll
            for (int nt = 0; nt < 2; nt++) {
                uint32_t bf[2] = { bq[nt], bq[nt + 2] };
#pragma unroll
                for (int mt = 0; mt < 2; mt++)
                    mma_f16(acc[mt][nt], af[mt], bf);
            }
        }

        if (it + 3 < nIter) load_stage((it + 3) % GSTH, it + 3);
        cpa_commit();
    }

#pragma unroll
    for (int mt = 0; mt < 2; mt++) {
        const int row = bm + wm + mt * 16 + (lane >> 2);
#pragma unroll
        for (int nt = 0; nt < 2; nt++) {
            const int col = bn + wn + nt * 8 + (lane & 3) * 2;
            *(float2*)(C + (size_t)row * ldc + col) =
                make_float2(acc[mt][nt][0], acc[mt][nt][1]);
            *(float2*)(C + (size_t)(row + 8) * ldc + col) =
                make_float2(acc[mt][nt][2], acc[mt][nt][3]);
        }
    }
}

// ---------------- merged pre-pass: MLP=8 per thread ----------------
#define NX4    (M_TOT * DM / 4)
#define NWIN4  (XZ_LD * DM / 4)
#define NWDT4  (DI * DI / 4)
#define NWXP4  (NX_PAD * DI / 4)
#define NWOUT4 (DM * DI / 4)
#define QX     (NX4 / 8)
#define QWIN   (NWIN4 / 8)
#define QWDT   (NWDT4 / 8)
#define QWXP   (NWXP4 / 8)
#define QWOUT  (NWOUT4 / 8)
#define QTOT   (QX + QWIN + QWDT + QWXP + QWOUT)

__device__ __forceinline__ void cvt8h(const float* __restrict__ src,
                                      __half* __restrict__ dst, int q, int Q) {
    float4 v[8];
#pragma unroll
    for (int k = 0; k < 8; k++) v[k] = ((const float4*)src)[q + k * Q];
#pragma unroll
    for (int k = 0; k < 8; k++) {
        const int i = q + k * Q;
        ((__half2*)dst)[i * 2]     = __floats2half2_rn(v[k].x, v[k].y);
        ((__half2*)dst)[i * 2 + 1] = __floats2half2_rn(v[k].z, v[k].w);
    }
}

__global__ __launch_bounds__(256)
void prepass_kernel(const float* __restrict__ x, const float* __restrict__ win,
                    const float* __restrict__ wdt, const float* __restrict__ wx,
                    const float* __restrict__ wout)
{
    int q = blockIdx.x * 256 + threadIdx.x;
    if (q >= QTOT) return;
    if (q < QX)                 { cvt8h(x, g_xh, q, QX); return; }
    if ((q -= QX) < QWIN)       { cvt8h(win, g_Winh, q, QWIN); return; }
    if ((q -= QWIN) < QWDT)     { cvt8h(wdt, g_Wdth, q, QWDT); return; }
    if ((q -= QWDT) < QWXP) {
        float4 v[8];
#pragma unroll
        for (int k = 0; k < 8; k++) {
            const int i = q + k * QWXP;
            const int n = i / (DI / 4);
            const int k4 = i % (DI / 4);
            v[k] = make_float4(0.f, 0.f, 0.f, 0.f);
            if (n < XDBL_LD) v[k] = ((const float4*)wx)[(size_t)n * (DI / 4) + k4];
        }
#pragma unroll
        for (int k = 0; k < 8; k++) {
            const int i = q + k * QWXP;
            ((__half2*)g_Wxh)[i * 2]     = __floats2half2_rn(v[k].x, v[k].y);
            ((__half2*)g_Wxh)[i * 2 + 1] = __floats2half2_rn(v[k].z, v[k].w);
        }
        return;
    }
    q -= QWXP;
    cvt8h(wout, g_Wouth, q, QWOUT);
}

// ---------------- depthwise causal conv + bias + SiLU -> both layouts ------
__global__ __launch_bounds__(256)
void conv_silu_T_kernel(const float* __restrict__ conv_w, const float* __restrict__ conv_b)
{
    __shared__ float s[32][133];
    __shared__ float r[128][33];
    const int t0 = blockIdx.x * 128;
    const int d0 = blockIdx.y * 32;
    const int b  = blockIdx.z;

    for (int tt = threadIdx.y; tt < 131; tt += 8) {
        const int gt = t0 - 3 + tt;
        float v = 0.f;
        if (gt >= 0)
            v = g_xin[(size_t)(b * SEQ + gt) * DI + d0 + threadIdx.x];
        s[threadIdx.x][tt] = v;
    }
    __syncthreads();

    for (int dd = threadIdx.y; dd < 32; dd += 8) {
        const int d = d0 + dd;
        const float w0 = conv_w[d * 4 + 0];
        const float w1 = conv_w[d * 4 + 1];
        const float w2 = conv_w[d * 4 + 2];
        const float w3 = conv_w[d * 4 + 3];
        const float cb = conv_b[d];
#pragma unroll
        for (int tc = 0; tc < 4; tc++) {
            const int tl = tc * 32 + threadIdx.x;
            float acc = cb;
            acc = fmaf(s[dd][tl + 0], w0, acc);
            acc = fmaf(s[dd][tl + 1], w1, acc);
            acc = fmaf(s[dd][tl + 2], w2, acc);
            acc = fmaf(s[dd][tl + 3], w3, acc);
            const float v = siluf(acc);
            g_xconvT[(size_t)d * M_TOT + b * SEQ + t0 + tl] = v;
            r[tl][dd] = v;
        }
    }
    __syncthreads();
    for (int tt = threadIdx.y; tt < 128; tt += 8)
        g_xconvh[(size_t)(b * SEQ + t0 + tt) * DI + d0 + threadIdx.x] =
            __float2half_rn(r[tt][threadIdx.x]);
}

// ---------------- fused selective scan (EXACT reference tree) ----------------
// Grid (DI/4, BATCH), 512 threads = 16 warps; warp n owns state n.
// B/C for the warp's state are cached in registers and reused across the
// 4 d-channels this CTA processes (cuts B/C L2 traffic 4x).
__global__ __launch_bounds__(512)
void scan_kernel(const float* __restrict__ A_log, const float* __restrict__ Dp)
{
    __shared__ float ss[16][520];
    const int d0 = blockIdx.x * 4, b = blockIdx.y;
    const int tid = threadIdx.x, warp = tid >> 5, lane = tid & 31;
    const int n = warp;
    const size_t nbase = (size_t)n * M_TOT + b * SEQ;
    const int t0 = lane * 16;

    // cache B, C for this warp's state (16 timesteps per lane)
    float Br[16], Cr[16];
#pragma unroll
    for (int q = 0; q < 4; q++) {
        *(float4*)&Br[q * 4] = *(const float4*)(g_BT  + nbase + t0 + q * 4);
        *(float4*)&Cr[q * 4] = *(const float4*)(g_CT2 + nbase + t0 + q * 4);
    }

    for (int dd = 0; dd < 4; dd++) {
        const int d = d0 + dd;
        const float a = -__expf(A_log[d * DS + n]);
        const size_t cbase = (size_t)d * M_TOT + b * SEQ;

        float c[16], v[16];
#pragma unroll
        for (int q = 0; q < 4; q++) {
            const float4 d4 = *(const float4*)(g_deltaT + cbase + t0 + q * 4);
            const float4 x4 = *(const float4*)(g_xconvT + cbase + t0 + q * 4);
            const float dv[4] = {d4.x, d4.y, d4.z, d4.w};
            const float xv[4] = {x4.x, x4.y, x4.z, x4.w};
#pragma unroll
            for (int i = 0; i < 4; i++) {
                c[q * 4 + i] = __expf(dv[i] * a) + 1e-12f;
                v[q * 4 + i] = fabsf(dv[i] * Br[q * 4 + i] * xv[i]) + 1e-12f;
            }
        }

        // up-sweep levels 0..3 (lane-local)
#pragma unroll
        for (int lev = 0; lev < 4; lev++) {
            const int half = 1 << lev;
#pragma unroll
            for (int r = 2 * half - 1; r < 16; r += 2 * half) {
                v[r] = v[r - half] + c[r] * v[r];
                c[r] = c[r - half] * c[r];
            }
        }
        // up-sweep levels 4..8 (cross-lane on element 15)
        float C15 = c[15], V15 = v[15];
#pragma unroll
        for (int sh = 1; sh <= 16; sh <<= 1) {
            const float cl = __shfl_up_sync(0xffffffffu, C15, sh);
            const float vl = __shfl_up_sync(0xffffffffu, V15, sh);
            if ((lane & (2 * sh - 1)) == (2 * sh - 1)) {
                V15 = vl + C15 * V15;
                C15 = cl * C15;
            }
        }
        // down-sweep levels 8..4 (gather both shfls BEFORE updating)
#pragma unroll
        for (int sh = 16; sh >= 1; sh >>= 1) {
            const float vl = __shfl_up_sync(0xffffffffu, V15, sh);
            const float vr = __shfl_down_sync(0xffffffffu, V15, sh);
            const int m = lane & (2 * sh - 1);
            float nv = V15;
            if (m == 2 * sh - 1) nv = vl + C15 * V15;
            else if (m == sh - 1) nv = vr;
            V15 = nv;
        }
        c[15] = C15;
        v[15] = V15;
        // down-sweep levels 3..0 (lane-local)
#pragma unroll
        for (int lev = 3; lev >= 0; lev--) {
            const int half = 1 << lev;
#pragma unroll
            for (int r = 2 * half - 1; r < 16; r += 2 * half) {
                const float tmp = v[r];
                v[r] = v[r - half] + c[r] * v[r];
                v[r - half] = tmp;
            }
        }

        // multiply by C, stage per-state rows to smem
#pragma unroll
        for (int q = 0; q < 4; q++) {
            float4 o;
            o.x = v[q * 4 + 0] * Cr[q * 4 + 0];
            o.y = v[q * 4 + 1] * Cr[q * 4 + 1];
            o.z = v[q * 4 + 2] * Cr[q * 4 + 2];
            o.w = v[q * 4 + 3] * Cr[q * 4 + 3];
            *(float4*)&ss[warp][t0 + q * 4] = o;
        }
        __syncthreads();

        // reduce over 16 states + epilogue; store half [d][bt] (coalesced)
        float acc = 0.f;
#pragma unroll
        for (int w = 0; w < 16; w++) acc += ss[w][tid];
        const float xct = g_xconvT[cbase + tid];
        const float gz  = g_zT[cbase + tid];
        g_ypreh[cbase + tid] = __float2half_rn(fmaf(xct, Dp[d], acc) * gz);
        __syncthreads();
    }
}

// ---------------- launch ----------------
extern "C" void kernel_launch(void* const* d_in, const int* in_sizes, int n_in,
                              void* d_out, int out_size)
{
    const float* x      = (const float*)d_in[0];
    const float* W_in   = (const float*)d_in[1];
    const float* conv_w = (const float*)d_in[2];
    const float* conv_b = (const float*)d_in[3];
    const float* W_x    = (const float*)d_in[4];
    const float* W_dt   = (const float*)d_in[5];
    const float* b_dt   = (const float*)d_in[6];
    const float* A_log  = (const float*)d_in[7];
    const float* Dp     = (const float*)d_in[8];
    const float* W_out  = (const float*)d_in[9];
    float* out = (float*)d_out;

    __half *xh, *Winh, *Wxh, *Wdth, *Wouth, *xconvh, *xdblh, *ypreh;
    float *deltaT;
    cudaGetSymbolAddress((void**)&xh,     g_xh);
    cudaGetSymbolAddress((void**)&Winh,   g_Winh);
    cudaGetSymbolAddress((void**)&Wxh,    g_Wxh);
    cudaGetSymbolAddress((void**)&Wdth,   g_Wdth);
    cudaGetSymbolAddress((void**)&Wouth,  g_Wouth);
    cudaGetSymbolAddress((void**)&xconvh, g_xconvh);
    cudaGetSymbolAddress((void**)&xdblh,  g_xdblh);
    cudaGetSymbolAddress((void**)&ypreh,  g_ypreh);
    cudaGetSymbolAddress((void**)&deltaT, g_deltaT);

    cudaFuncSetAttribute((const void*)hgemm<1>, cudaFuncAttributeMaxDynamicSharedMemorySize, HSMEM);
    cudaFuncSetAttribute((const void*)hgemm<2>, cudaFuncAttributeMaxDynamicSharedMemorySize, HSMEM);
    cudaFuncSetAttribute((const void*)hgemm<3>, cudaFuncAttributeMaxDynamicSharedMemorySize, HSMEM);
    cudaFuncSetAttribute((const void*)hgemm_g6, cudaFuncAttributeMaxDynamicSharedMemorySize, G6SMEM);

    // 0) merged pre-pass (MLP=8)
    prepass_kernel<<<(QTOT + 255) / 256, 256>>>(x, W_in, W_dt, W_x, W_out);

    // 1) xz = x @ W_in^T ; x_inner -> g_xin, z -> silu -> g_zT
    hgemm<2><<<dim3(XZ_LD / 128, M_TOT / 64), 256, HSMEM>>>(
        xh, DM, Winh, DM, nullptr, nullptr, 0, DM);

    // 2) conv + silu -> xconvT (f32) + xconvh (half)
    conv_silu_T_kernel<<<dim3(SEQ / 128, DI / 32, BATCH), dim3(32, 8)>>>(conv_w, conv_b);

    // 3) x_dbl = x_conv @ W_x^T ; delta_raw -> xdblh, B -> BT, C -> CT2
    hgemm<3><<<dim3(NX_PAD / 128, M_TOT / 64), 256, HSMEM>>>(
        xconvh, DI, Wxh, DI, nullptr, nullptr, 0, DI);

    // 4) deltaT = softplus(delta_raw @ W_dt^T + b_dt), transposed store
    hgemm<1><<<dim3(DI / 128, M_TOT / 64), 256, HSMEM>>>(
        xdblh, DI, Wdth, DI, b_dt, deltaT, M_TOT, DI);

    // 5) fused selective scan (exact reference tree, 4 d per CTA) -> ypreh
    scan_kernel<<<dim3(DI / 4, BATCH), 512>>>(A_log, Dp);

    // 6) out = ypre @ W_out^T (A k-major via ldmatrix.trans)
    hgemm_g6<<<dim3(DM / 64, M_TOT / 64), 256, G6SMEM>>>(
        ypreh, Wouth, out, DM, DI);
}

// round 17
// speedup vs baseline: 1.0263x; 1.0263x over previous
#include <cuda_runtime.h>
#include <cuda_fp16.h>
#include <math.h>
#include <stdint.h>

// ---------------- problem constants ----------------
#define BATCH   2
#define SEQ     512
#define DM      768
#define DI      1536
#define DS      16
#define M_TOT   (BATCH*SEQ)   // 1024
#define XZ_LD   (2*DI)        // 3072
#define XDBL_LD (DI + 2*DS)   // 1568
#define NX_PAD  1664

// ---------------- scratch ----------------
__device__ __half g_xh    [M_TOT * DM];
__device__ __half g_Winh  [XZ_LD * DM];
__device__ __half g_Wxh   [NX_PAD * DI];
__device__ __half g_Wdth  [DI * DI];
__device__ __half g_Wouth [DM * DI];
__device__ __half g_xconvh[M_TOT * DI];
__device__ __half g_xdblh [M_TOT * DI];
__device__ __half g_ypreh [DI * M_TOT];     // [d][bt] (k-major for G6 A)
__device__ float  g_xin   [M_TOT * DI];
__device__ float  g_zT    [DI * M_TOT];
__device__ float  g_xconvT[DI * M_TOT];
__device__ float  g_BT    [DS * M_TOT];
__device__ float  g_CT2   [DS * M_TOT];
__device__ float  g_deltaT[DI * M_TOT];

// ---------------- helpers (fast transcendental intrinsics) ----------------
__device__ __forceinline__ float softplusf(float x) {
    if (x > 20.f) return x;
    return __logf(1.f + __expf(x));
}
__device__ __forceinline__ float siluf(float x) {
    return x / (1.f + __expf(-x));
}
__device__ __forceinline__ void cpa16(uint32_t dst, const void* src) {
    asm volatile("cp.async.cg.shared.global [%0], [%1], 16;\n" :: "r"(dst), "l"(src));
}
__device__ __forceinline__ void cpa_commit() {
    asm volatile("cp.async.commit_group;\n" ::: "memory");
}
__device__ __forceinline__ void ldmx4(uint32_t* r, uint32_t addr) {
    asm volatile(
        "ldmatrix.sync.aligned.m8n8.x4.shared.b16 {%0,%1,%2,%3}, [%4];"
        : "=r"(r[0]), "=r"(r[1]), "=r"(r[2]), "=r"(r[3]) : "r"(addr));
}
__device__ __forceinline__ void ldmx4t(uint32_t* r, uint32_t addr) {
    asm volatile(
        "ldmatrix.sync.aligned.m8n8.x4.trans.shared.b16 {%0,%1,%2,%3}, [%4];"
        : "=r"(r[0]), "=r"(r[1]), "=r"(r[2]), "=r"(r[3]) : "r"(addr));
}
__device__ __forceinline__ void mma_f16(float* c, const uint32_t* a, const uint32_t* b) {
    asm volatile(
        "mma.sync.aligned.m16n8k16.row.col.f32.f16.f16.f32 "
        "{%0,%1,%2,%3}, {%4,%5,%6,%7}, {%8,%9}, {%0,%1,%2,%3};"
        : "+f"(c[0]), "+f"(c[1]), "+f"(c[2]), "+f"(c[3])
        : "r"(a[0]), "r"(a[1]), "r"(a[2]), "r"(a[3]), "r"(b[0]), "r"(b[1]));
}

// ---------------- fp16 GEMM: act(A @ W^T), BK=64 ----------------
// A row-major [1024,K] half, W row-major [N,K] half. 64x128x64 tile,
// 256 threads = 8 warps of 32x32, 2 CTAs/SM, ldmatrix fragments,
// 4-stage cp.async, 3 in flight, ONE __syncthreads per k-iter.
// Buffer written at iter it ((it+3)%4) was last read at iter it-1; every
// warp finished those reads before the barrier at the start of it -> safe.
#define GSTH 4
#define AROWK 72                               // 64 halves + 8 pad
#define HSTG_B ((64 + 128) * AROWK * 2)        // 27648 B per stage
#define HSMEM  (GSTH * HSTG_B)                 // 110592 B

template<int EPI>
__global__ __launch_bounds__(256, 2)
void hgemm(const __half* __restrict__ A, int lda,
           const __half* __restrict__ W, int ldw,
           const float* __restrict__ bias,
           float* __restrict__ C, int ldc, int K)
{
    extern __shared__ __align__(16) char smem[];
    const int tid = threadIdx.x, warp = tid >> 5, lane = tid & 31;
    const int bm = blockIdx.y * 64, bn = blockIdx.x * 128;
    const int wm = (warp & 1) * 32, wn = (warp >> 1) * 32;
    const uint32_t sbase = (uint32_t)__cvta_generic_to_shared(smem);

    const int lrow8 = (lane & 7) + ((lane >> 3) & 1) * 8;
    const int lk8   = (lane >> 4) * 8;

    float acc[2][4][4];
#pragma unroll
    for (int i = 0; i < 2; i++)
#pragma unroll
        for (int j = 0; j < 4; j++)
#pragma unroll
            for (int k = 0; k < 4; k++) acc[i][j][k] = 0.f;

    const int nIter = K / 64;

    auto load_stage = [&](int s, int kt) {
        const uint32_t aB = sbase + (uint32_t)s * HSTG_B;
        const uint32_t bB = aB + 64 * AROWK * 2;
        // A: 64 rows x 8 chunks = 512 -> 2/thread
#pragma unroll
        for (int p = 0; p < 2; p++) {
            const int idx = tid + p * 256;
            const int row = idx >> 3, ch = idx & 7;
            cpa16(aB + (uint32_t)(row * AROWK + ch * 8) * 2,
                  A + (size_t)(bm + row) * lda + kt * 64 + ch * 8);
        }
        // B: 128 rows x 8 chunks = 1024 -> 4/thread
#pragma unroll
        for (int p = 0; p < 4; p++) {
            const int idx = tid + p * 256;
            const int row = idx >> 3, ch = idx & 7;
            cpa16(bB + (uint32_t)(row * AROWK + ch * 8) * 2,
                  W + (size_t)(bn + row) * ldw + kt * 64 + ch * 8);
        }
    };

    load_stage(0, 0); cpa_commit();
    load_stage(1, 1); cpa_commit();
    load_stage(2, 2); cpa_commit();

    for (int it = 0; it < nIter; it++) {
        asm volatile("cp.async.wait_group 2;\n" ::: "memory");
        __syncthreads();

        const uint32_t stg = sbase + (uint32_t)(it % GSTH) * HSTG_B;
        const uint32_t stgB = stg + 64 * AROWK * 2;

#pragma unroll
        for (int ks = 0; ks < 4; ks++) {
            uint32_t af[2][4], bq[2][4];
#pragma unroll
            for (int mt = 0; mt < 2; mt++)
                ldmx4(af[mt],
                      stg + (uint32_t)((wm + mt * 16 + lrow8) * AROWK + ks * 16 + lk8) * 2);
#pragma unroll
            for (int nh = 0; nh < 2; nh++)
                ldmx4(bq[nh],
                      stgB + (uint32_t)((wn + nh * 16 + lrow8) * AROWK + ks * 16 + lk8) * 2);
#pragma unroll
            for (int nt = 0; nt < 4; nt++) {
                uint32_t bf[2] = { bq[nt >> 1][nt & 1], bq[nt >> 1][(nt & 1) + 2] };
#pragma unroll
                for (int mt = 0; mt < 2; mt++)
                    mma_f16(acc[mt][nt], af[mt], bf);
            }
        }

        if (it + 3 < nIter) load_stage((it + 3) % GSTH, it + 3);
        cpa_commit();
    }

    // ---- epilogue ----
#pragma unroll
    for (int mt = 0; mt < 2; mt++) {
        const int row = bm + wm + mt * 16 + (lane >> 2);
#pragma unroll
        for (int nt = 0; nt < 4; nt++) {
            const int col = bn + wn + nt * 8 + (lane & 3) * 2;
            const float v0 = acc[mt][nt][0], v1 = acc[mt][nt][1];
            const float v2 = acc[mt][nt][2], v3 = acc[mt][nt][3];
            if (EPI == 1) {
                const float b0 = bias[col], b1 = bias[col + 1];
                C[(size_t)col * ldc + row]            = softplusf(v0 + b0);
                C[(size_t)(col + 1) * ldc + row]      = softplusf(v1 + b1);
                C[(size_t)col * ldc + row + 8]        = softplusf(v2 + b0);
                C[(size_t)(col + 1) * ldc + row + 8]  = softplusf(v3 + b1);
            } else if (EPI == 2) {
                if (col < DI) {
                    *(float2*)(g_xin + (size_t)row * DI + col)       = make_float2(v0, v1);
                    *(float2*)(g_xin + (size_t)(row + 8) * DI + col) = make_float2(v2, v3);
                } else {
                    const int dd = col - DI;
                    g_zT[(size_t)dd * M_TOT + row]           = siluf(v0);
                    g_zT[(size_t)(dd + 1) * M_TOT + row]     = siluf(v1);
                    g_zT[(size_t)dd * M_TOT + row + 8]       = siluf(v2);
                    g_zT[(size_t)(dd + 1) * M_TOT + row + 8] = siluf(v3);
                }
            } else {  // EPI == 3
                if (col < DI) {
                    *(__half2*)(g_xdblh + (size_t)row * DI + col)       = __floats2half2_rn(v0, v1);
                    *(__half2*)(g_xdblh + (size_t)(row + 8) * DI + col) = __floats2half2_rn(v2, v3);
                } else if (col < DI + DS) {
                    const int nn = col - DI;
                    g_BT[(size_t)nn * M_TOT + row]           = v0;
                    g_BT[(size_t)(nn + 1) * M_TOT + row]     = v1;
                    g_BT[(size_t)nn * M_TOT + row + 8]       = v2;
                    g_BT[(size_t)(nn + 1) * M_TOT + row + 8] = v3;
                } else if (col < DI + 2 * DS) {
                    const int nn = col - DI - DS;
                    g_CT2[(size_t)nn * M_TOT + row]           = v0;
                    g_CT2[(size_t)(nn + 1) * M_TOT + row]     = v1;
                    g_CT2[(size_t)nn * M_TOT + row + 8]       = v2;
                    g_CT2[(size_t)(nn + 1) * M_TOT + row + 8] = v3;
                }
            }
        }
    }
}

// ---------------- G6: out = ypre @ W_out^T, A stored k-major [DI][1024] ----
#define AROWH 40                                   // 32 halves + 8 pad
#define AROWM 72                                   // 64 m-halves + 8 pad
#define G6ST 5
#define G6STG ((32 * AROWM + 64 * AROWH) * 2)      // 9728 B
#define G6SMEM (G6ST * G6STG)                      // 48640 B

__global__ __launch_bounds__(256, 2)
void hgemm_g6(const __half* __restrict__ AT,   // [K][1024]
              const __half* __restrict__ W,    // [DM][K]
              float* __restrict__ C, int ldc, int K)
{
    extern __shared__ __align__(16) char smem[];
    const int tid = threadIdx.x, warp = tid >> 5, lane = tid & 31;
    const int bm = blockIdx.y * 64, bn = blockIdx.x * 64;
    const int wm = (warp & 1) * 32, wn = (warp >> 1) * 16;
    const uint32_t sbase = (uint32_t)__cvta_generic_to_shared(smem);

    const int lrow8 = (lane & 7) + ((lane >> 3) & 1) * 8;
    const int lk8   = (lane >> 4) * 8;
    const int trow = (lane & 7) + ((lane >> 4) & 1) * 8;
    const int tcol = ((lane >> 3) & 1) * 8;

    float acc[2][2][4];
#pragma unroll
    for (int i = 0; i < 2; i++)
#pragma unroll
        for (int j = 0; j < 2; j++)
#pragma unroll
            for (int k = 0; k < 4; k++) acc[i][j][k] = 0.f;

    const int nIter = K / 32;

    auto load_stage = [&](int s, int kt) {
        const uint32_t aB = sbase + (uint32_t)s * G6STG;
        const uint32_t bB = aB + 32 * AROWM * 2;
        {
            const int row = tid >> 3, ch = tid & 7;
            cpa16(aB + (uint32_t)(row * AROWM + ch * 8) * 2,
                  AT + (size_t)(kt * 32 + row) * M_TOT + bm + ch * 8);
        }
        {
            const int row = tid >> 2, ch = tid & 3;
            cpa16(bB + (uint32_t)(row * AROWH + ch * 8) * 2,
                  W + (size_t)(bn + row) * K + kt * 32 + ch * 8);
        }
    };

    load_stage(0, 0); cpa_commit();
    load_stage(1, 1); cpa_commit();
    load_stage(2, 2); cpa_commit();

    for (int it = 0; it < nIter; it++) {
        asm volatile("cp.async.wait_group 2;\n" ::: "memory");
        __syncthreads();

        const uint32_t stg = sbase + (uint32_t)(it % G6ST) * G6STG;
        const uint32_t stgB = stg + 32 * AROWM * 2;

#pragma unroll
        for (int ks = 0; ks < 2; ks++) {
            uint32_t af[2][4], bq[4];
#pragma unroll
            for (int mt = 0; mt < 2; mt++)
                ldmx4t(af[mt],
                       stg + (uint32_t)((ks * 16 + trow) * AROWM + wm + mt * 16 + tcol) * 2);
            ldmx4(bq, stgB + (uint32_t)((wn + lrow8) * AROWH + ks * 16 + lk8) * 2);
#pragma unroll
            for (int nt = 0; nt < 2; nt++) {
                uint32_t bf[2] = { bq[nt], bq[nt + 2] };
#pragma unroll
                for (int mt = 0; mt < 2; mt++)
                    mma_f16(acc[mt][nt], af[mt], bf);
            }
        }

        if (it + 3 < nIter) load_stage((it + 3) % G6ST, it + 3);
        cpa_commit();
    }

#pragma unroll
    for (int mt = 0; mt < 2; mt++) {
        const int row = bm + wm + mt * 16 + (lane >> 2);
#pragma unroll
        for (int nt = 0; nt < 2; nt++) {
            const int col = bn + wn + nt * 8 + (lane & 3) * 2;
            *(float2*)(C + (size_t)row * ldc + col) =
                make_float2(acc[mt][nt][0], acc[mt][nt][1]);
            *(float2*)(C + (size_t)(row + 8) * ldc + col) =
                make_float2(acc[mt][nt][2], acc[mt][nt][3]);
        }
    }
}

// ---------------- merged pre-pass: MLP=4 per thread ----------------
#define NX4    (M_TOT * DM / 4)
#define NWIN4  (XZ_LD * DM / 4)
#define NWDT4  (DI * DI / 4)
#define NWXP4  (NX_PAD * DI / 4)
#define NWOUT4 (DM * DI / 4)
#define QX     (NX4 / 4)
#define QWIN   (NWIN4 / 4)
#define QWDT   (NWDT4 / 4)
#define QWXP   (NWXP4 / 4)
#define QWOUT  (NWOUT4 / 4)
#define QTOT   (QX + QWIN + QWDT + QWXP + QWOUT)

__device__ __forceinline__ void cvt4h(const float* __restrict__ src,
                                      __half* __restrict__ dst, int q, int Q) {
    float4 v[4];
#pragma unroll
    for (int k = 0; k < 4; k++) v[k] = ((const float4*)src)[q + k * Q];
#pragma unroll
    for (int k = 0; k < 4; k++) {
        const int i = q + k * Q;
        ((__half2*)dst)[i * 2]     = __floats2half2_rn(v[k].x, v[k].y);
        ((__half2*)dst)[i * 2 + 1] = __floats2half2_rn(v[k].z, v[k].w);
    }
}

__global__ __launch_bounds__(256)
void prepass_kernel(const float* __restrict__ x, const float* __restrict__ win,
                    const float* __restrict__ wdt, const float* __restrict__ wx,
                    const float* __restrict__ wout)
{
    int q = blockIdx.x * 256 + threadIdx.x;
    if (q >= QTOT) return;
    if (q < QX)                 { cvt4h(x, g_xh, q, QX); return; }
    if ((q -= QX) < QWIN)       { cvt4h(win, g_Winh, q, QWIN); return; }
    if ((q -= QWIN) < QWDT)     { cvt4h(wdt, g_Wdth, q, QWDT); return; }
    if ((q -= QWDT) < QWXP) {
        float4 v[4];
#pragma unroll
        for (int k = 0; k < 4; k++) {
            const int i = q + k * QWXP;
            const int n = i / (DI / 4);
            const int k4 = i % (DI / 4);
            v[k] = make_float4(0.f, 0.f, 0.f, 0.f);
            if (n < XDBL_LD) v[k] = ((const float4*)wx)[(size_t)n * (DI / 4) + k4];
        }
#pragma unroll
        for (int k = 0; k < 4; k++) {
            const int i = q + k * QWXP;
            ((__half2*)g_Wxh)[i * 2]     = __floats2half2_rn(v[k].x, v[k].y);
            ((__half2*)g_Wxh)[i * 2 + 1] = __floats2half2_rn(v[k].z, v[k].w);
        }
        return;
    }
    q -= QWXP;
    cvt4h(wout, g_Wouth, q, QWOUT);
}

// ---------------- depthwise causal conv + bias + SiLU -> both layouts ------
__global__ __launch_bounds__(256)
void conv_silu_T_kernel(const float* __restrict__ conv_w, const float* __restrict__ conv_b)
{
    __shared__ float s[32][133];
    __shared__ float r[128][33];
    const int t0 = blockIdx.x * 128;
    const int d0 = blockIdx.y * 32;
    const int b  = blockIdx.z;

    for (int tt = threadIdx.y; tt < 131; tt += 8) {
        const int gt = t0 - 3 + tt;
        float v = 0.f;
        if (gt >= 0)
            v = g_xin[(size_t)(b * SEQ + gt) * DI + d0 + threadIdx.x];
        s[threadIdx.x][tt] = v;
    }
    __syncthreads();

    for (int dd = threadIdx.y; dd < 32; dd += 8) {
        const int d = d0 + dd;
        const float w0 = conv_w[d * 4 + 0];
        const float w1 = conv_w[d * 4 + 1];
        const float w2 = conv_w[d * 4 + 2];
        const float w3 = conv_w[d * 4 + 3];
        const float cb = conv_b[d];
#pragma unroll
        for (int tc = 0; tc < 4; tc++) {
            const int tl = tc * 32 + threadIdx.x;
            float acc = cb;
            acc = fmaf(s[dd][tl + 0], w0, acc);
            acc = fmaf(s[dd][tl + 1], w1, acc);
            acc = fmaf(s[dd][tl + 2], w2, acc);
            acc = fmaf(s[dd][tl + 3], w3, acc);
            const float v = siluf(acc);
            g_xconvT[(size_t)d * M_TOT + b * SEQ + t0 + tl] = v;
            r[tl][dd] = v;
        }
    }
    __syncthreads();
    for (int tt = threadIdx.y; tt < 128; tt += 8)
        g_xconvh[(size_t)(b * SEQ + t0 + tt) * DI + d0 + threadIdx.x] =
            __float2half_rn(r[tt][threadIdx.x]);
}

// ---------------- fused selective scan (EXACT reference tree) ----------------
__global__ __launch_bounds__(512)
void scan_kernel(const float* __restrict__ A_log, const float* __restrict__ Dp)
{
    __shared__ float ss[16][520];
    const int d = blockIdx.x, b = blockIdx.y;
    const int tid = threadIdx.x, warp = tid >> 5, lane = tid & 31;
    const int n = warp;
    const float a = -__expf(A_log[d * DS + n]);
    const size_t cbase = (size_t)d * M_TOT + b * SEQ;
    const size_t nbase = (size_t)n * M_TOT + b * SEQ;
    const int t0 = lane * 16;

    float c[16], v[16];
#pragma unroll
    for (int q = 0; q < 4; q++) {
        const float4 d4 = *(const float4*)(g_deltaT + cbase + t0 + q * 4);
        const float4 x4 = *(const float4*)(g_xconvT + cbase + t0 + q * 4);
        const float4 b4 = *(const float4*)(g_BT + nbase + t0 + q * 4);
        const float dv[4] = {d4.x, d4.y, d4.z, d4.w};
        const float xv[4] = {x4.x, x4.y, x4.z, x4.w};
        const float bv[4] = {b4.x, b4.y, b4.z, b4.w};
#pragma unroll
        for (int i = 0; i < 4; i++) {
            c[q * 4 + i] = __expf(dv[i] * a) + 1e-12f;
            v[q * 4 + i] = fabsf(dv[i] * bv[i] * xv[i]) + 1e-12f;
        }
    }

    // up-sweep levels 0..3 (lane-local)
#pragma unroll
    for (int lev = 0; lev < 4; lev++) {
        const int half = 1 << lev;
#pragma unroll
        for (int r = 2 * half - 1; r < 16; r += 2 * half) {
            v[r] = v[r - half] + c[r] * v[r];
            c[r] = c[r - half] * c[r];
        }
    }

    // up-sweep levels 4..8 (cross-lane on element 15)
    float C15 = c[15], V15 = v[15];
#pragma unroll
    for (int dd = 1; dd <= 16; dd <<= 1) {
        const float cl = __shfl_up_sync(0xffffffffu, C15, dd);
        const float vl = __shfl_up_sync(0xffffffffu, V15, dd);
        if ((lane & (2 * dd - 1)) == (2 * dd - 1)) {
            V15 = vl + C15 * V15;
            C15 = cl * C15;
        }
    }

    // down-sweep levels 8..4 (gather both shfls BEFORE updating)
#pragma unroll
    for (int dd = 16; dd >= 1; dd >>= 1) {
        const float vl = __shfl_up_sync(0xffffffffu, V15, dd);
        const float vr = __shfl_down_sync(0xffffffffu, V15, dd);
        const int m = lane & (2 * dd - 1);
        float nv = V15;
        if (m == 2 * dd - 1) nv = vl + C15 * V15;
        else if (m == dd - 1) nv = vr;
        V15 = nv;
    }
    c[15] = C15;
    v[15] = V15;

    // down-sweep levels 3..0 (lane-local)
#pragma unroll
    for (int lev = 3; lev >= 0; lev--) {
        const int half = 1 << lev;
#pragma unroll
        for (int r = 2 * half - 1; r < 16; r += 2 * half) {
            const float tmp = v[r];
            v[r] = v[r - half] + c[r] * v[r];
            v[r - half] = tmp;
        }
    }

    // multiply by C, stage per-state rows to smem
#pragma unroll
    for (int q = 0; q < 4; q++) {
        const float4 c4 = *(const float4*)(g_CT2 + nbase + t0 + q * 4);
        float4 o;
        o.x = v[q * 4 + 0] * c4.x;
        o.y = v[q * 4 + 1] * c4.y;
        o.z = v[q * 4 + 2] * c4.z;
        o.w = v[q * 4 + 3] * c4.w;
        *(float4*)&ss[warp][t0 + q * 4] = o;
    }
    __syncthreads();

    // reduce over 16 states + epilogue; store half [d][bt] (coalesced)
    float acc = 0.f;
#pragma unroll
    for (int w = 0; w < 16; w++) acc += ss[w][tid];
    const float xct = g_xconvT[cbase + tid];
    const float gz  = g_zT[cbase + tid];
    g_ypreh[cbase + tid] = __float2half_rn(fmaf(xct, Dp[d], acc) * gz);
}

// ---------------- launch ----------------
extern "C" void kernel_launch(void* const* d_in, const int* in_sizes, int n_in,
                              void* d_out, int out_size)
{
    const float* x      = (const float*)d_in[0];
    const float* W_in   = (const float*)d_in[1];
    const float* conv_w = (const float*)d_in[2];
    const float* conv_b = (const float*)d_in[3];
    const float* W_x    = (const float*)d_in[4];
    const float* W_dt   = (const float*)d_in[5];
    const float* b_dt   = (const float*)d_in[6];
    const float* A_log  = (const float*)d_in[7];
    const float* Dp     = (const float*)d_in[8];
    const float* W_out  = (const float*)d_in[9];
    float* out = (float*)d_out;

    __half *xh, *Winh, *Wxh, *Wdth, *Wouth, *xconvh, *xdblh, *ypreh;
    float *deltaT;
    cudaGetSymbolAddress((void**)&xh,     g_xh);
    cudaGetSymbolAddress((void**)&Winh,   g_Winh);
    cudaGetSymbolAddress((void**)&Wxh,    g_Wxh);
    cudaGetSymbolAddress((void**)&Wdth,   g_Wdth);
    cudaGetSymbolAddress((void**)&Wouth,  g_Wouth);
    cudaGetSymbolAddress((void**)&xconvh, g_xconvh);
    cudaGetSymbolAddress((void**)&xdblh,  g_xdblh);
    cudaGetSymbolAddress((void**)&ypreh,  g_ypreh);
    cudaGetSymbolAddress((void**)&deltaT, g_deltaT);

    cudaFuncSetAttribute((const void*)hgemm<1>, cudaFuncAttributeMaxDynamicSharedMemorySize, HSMEM);
    cudaFuncSetAttribute((const void*)hgemm<2>, cudaFuncAttributeMaxDynamicSharedMemorySize, HSMEM);
    cudaFuncSetAttribute((const void*)hgemm<3>, cudaFuncAttributeMaxDynamicSharedMemorySize, HSMEM);
    cudaFuncSetAttribute((const void*)hgemm_g6, cudaFuncAttributeMaxDynamicSharedMemorySize, G6SMEM);

    // 0) merged pre-pass
    prepass_kernel<<<(QTOT + 255) / 256, 256>>>(x, W_in, W_dt, W_x, W_out);

    // 1) xz = x @ W_in^T ; x_inner -> g_xin, z -> silu -> g_zT
    hgemm<2><<<dim3(XZ_LD / 128, M_TOT / 64), 256, HSMEM>>>(
        xh, DM, Winh, DM, nullptr, nullptr, 0, DM);

    // 2) conv + silu -> xconvT (f32) + xconvh (half)
    conv_silu_T_kernel<<<dim3(SEQ / 128, DI / 32, BATCH), dim3(32, 8)>>>(conv_w, conv_b);

    // 3) x_dbl = x_conv @ W_x^T ; delta_raw -> xdblh, B -> BT, C -> CT2
    hgemm<3><<<dim3(NX_PAD / 128, M_TOT / 64), 256, HSMEM>>>(
        xconvh, DI, Wxh, DI, nullptr, nullptr, 0, DI);

    // 4) deltaT = softplus(delta_raw @ W_dt^T + b_dt), transposed store
    hgemm<1><<<dim3(DI / 128, M_TOT / 64), 256, HSMEM>>>(
        xdblh, DI, Wdth, DI, b_dt, deltaT, M_TOT, DI);

    // 5) fused selective scan (exact reference tree) -> ypreh (half [d][bt])
    scan_kernel<<<dim3(DI, BATCH), 512>>>(A_log, Dp);

    // 6) out = ypre @ W_out^T (A k-major via ldmatrix.trans)
    hgemm_g6<<<dim3(DM / 64, M_TOT / 64), 256, G6SMEM>>>(
        ypreh, Wouth, out, DM, DI);
}